// round 10
// baseline (speedup 1.0000x reference)
#include <cuda_runtime.h>

// Blur_by_Kernel: per-batch 21x21 cross-correlation, reflect pad 10.
// input (16,3,768,768) fp32, kernel (16,21,21) fp32.
// out[b,c,y,x] = sum_{ky,kx} in[b,c, refl(y+ky-10), refl(x+kx-10)] * w[b,ky,kx]
//
// R10 = R9 (427.6us: 128-thread CTAs, 128x32 tile, 6 CTAs/SM, scalar-FFMA
// sliding window, vectorized interior prologue) + ONE change: XOR-swizzled
// tile layout (off ^ ((off>>3)&0x70), 16B units, 1024B-aligned base).
// R9's window LDS.128s were 2-way bank-conflicted (lanes tx, tx+4 share bank
// quads): 8 cyc/load instead of 4. Swizzle makes each 8-lane phase group hit
// 8 distinct bank quads -> conflict-free window loads.

namespace {
constexpr int HW   = 768;
constexpr int KS   = 21;
constexpr int PAD  = 10;
constexpr int CPT  = 8;                  // cols per thread
constexpr int RPT  = 4;                  // rows per thread
constexpr int TXN  = 16, TYN = 8;
constexpr int TILE_X = CPT * TXN;        // 128
constexpr int TILE_Y = RPT * TYN;        // 32
constexpr int SM_W = TILE_X + 2 * PAD;   // 148 floats (592B rows)
constexpr int SM_H = TILE_Y + 2 * PAD;   // 52 rows
constexpr int WSTRIDE = 24;              // padded weight row (96B)
constexpr int NT   = TXN * TYN;          // 128
constexpr int FPR  = 38;                 // float4 units per row in fast path
}

__device__ __forceinline__ int swz(int boff) {
    return boff ^ ((boff >> 3) & 0x70);
}
__device__ __forceinline__ void sts_swz(float* base, int boff, float val) {
    *(float*)((char*)base + swz(boff)) = val;
}

// one weight-row pass: acc[j] += sum_kx v[kx+j] * w[kx]
__device__ __forceinline__ void do_pass(float (&acc)[CPT],
                                        const float* __restrict__ wr,
                                        const float (&v)[28])
{
    #pragma unroll
    for (int g = 0; g < 5; ++g) {
        const float4 w = *(const float4*)(wr + 4 * g);   // broadcast LDS.128
        #pragma unroll
        for (int j = 0; j < CPT; ++j) acc[j] = fmaf(v[4*g + 0 + j], w.x, acc[j]);
        #pragma unroll
        for (int j = 0; j < CPT; ++j) acc[j] = fmaf(v[4*g + 1 + j], w.y, acc[j]);
        #pragma unroll
        for (int j = 0; j < CPT; ++j) acc[j] = fmaf(v[4*g + 2 + j], w.z, acc[j]);
        #pragma unroll
        for (int j = 0; j < CPT; ++j) acc[j] = fmaf(v[4*g + 3 + j], w.w, acc[j]);
    }
    const float wl = wr[20];
    #pragma unroll
    for (int j = 0; j < CPT; ++j) acc[j] = fmaf(v[20 + j], wl, acc[j]);
}

__global__ __launch_bounds__(NT, 6)
void blur21_kernel(const float* __restrict__ in,
                   const float* __restrict__ wts,
                   float* __restrict__ out)
{
    __shared__ __align__(1024) float tile[SM_H * SM_W];
    __shared__ float sw[KS * WSTRIDE];

    const int bc  = blockIdx.z;           // b*3 + c
    const int b   = bc / 3;
    const int bx  = blockIdx.x * TILE_X;
    const int by  = blockIdx.y * TILE_Y;
    const int tid = threadIdx.x;

    const float* __restrict__ img = in + (size_t)bc * (HW * HW);

    // weights for this batch, rows padded to WSTRIDE (504 floats, unswizzled)
    for (int i = tid; i < KS * WSTRIDE; i += NT) {
        const int r = i / WSTRIDE, c = i - r * WSTRIDE;
        sw[i] = (c < KS) ? wts[b * (KS * KS) + r * KS + c] : 0.f;
    }

    if (bx >= TILE_X && bx + TILE_X + PAD <= HW) {
        // ---- fast prologue: no x-reflection possible for this block ----
        // gmem span [bx-12, bx+140), 16B-aligned; warp w does rows w,w+4,...
        const int w   = tid >> 5;
        const int ln  = tid & 31;
        const float* __restrict__ base = img + bx - 12;
        #pragma unroll
        for (int k = 0; k < 13; ++k) {
            const int r = w + 4 * k;
            int gy = by + r - PAD;
            gy = (gy < 0) ? -gy : ((gy >= HW) ? (2 * HW - 2 - gy) : gy);
            const float4* __restrict__ gp = (const float4*)(base + (size_t)gy * HW);
            const int rb = r * SM_W * 4;               // row byte base

            {   // unit u = ln (0..31); tile cols c0..c0+3, c0 = 4*ln - 2
                const float4 q = gp[ln];
                const int c0 = 4 * ln - 2;
                const int o  = rb + 4 * c0;
                if (c0 >= 0)     sts_swz(tile, o,      q.x);
                if (c0 + 1 >= 0) sts_swz(tile, o + 4,  q.y);
                sts_swz(tile, o + 8,  q.z);
                sts_swz(tile, o + 12, q.w);
            }
            if (ln < FPR - 32) {                       // unit u = 32+ln (32..37)
                const float4 q = gp[32 + ln];
                const int c0 = 4 * (32 + ln) - 2;      // 126..146
                const int o  = rb + 4 * c0;
                sts_swz(tile, o,     q.x);
                sts_swz(tile, o + 4, q.y);
                if (c0 + 2 < SM_W) sts_swz(tile, o + 8,  q.z);
                if (c0 + 3 < SM_W) sts_swz(tile, o + 12, q.w);
            }
        }
    } else {
        // ---- edge prologue (bx==0 or bx==640): scalar reflect path ----
        int r = 0, c = tid;               // NT <= SM_W so first row covers tid
        for (int i = tid; i < SM_H * SM_W; i += NT) {
            int gy = by + r - PAD;
            gy = (gy < 0) ? -gy : ((gy >= HW) ? (2 * HW - 2 - gy) : gy);
            int gx = bx + c - PAD;
            gx = (gx < 0) ? -gx : ((gx >= HW) ? (2 * HW - 2 - gx) : gx);
            sts_swz(tile, 4 * i, img[gy * HW + gx]);
            c += NT;
            if (c >= SM_W) { c -= SM_W; ++r; }
        }
    }
    __syncthreads();

    const int tx = tid & 15;              // 0..15
    const int ty = tid >> 4;              // 0..7
    const int ox = tx * CPT;              // 32B-aligned tile col base
    const int oy = ty * RPT;

    float acc0[CPT], acc1[CPT], acc2[CPT], acc3[CPT];
    #pragma unroll
    for (int j = 0; j < CPT; ++j) {
        acc0[j] = 0.f; acc1[j] = 0.f; acc2[j] = 0.f; acc3[j] = 0.f;
    }

    float v[28];
    #define LOADW(s)                                                     \
        do {                                                             \
            const int boff = ((oy + (s)) * SM_W + ox) * 4;               \
            _Pragma("unroll")                                            \
            for (int i = 0; i < 7; ++i) {                                \
                const int o = boff + 16 * i;                             \
                const float4 q = *(const float4*)((const char*)tile      \
                                                  + swz(o));             \
                v[4*i+0] = q.x; v[4*i+1] = q.y;                          \
                v[4*i+2] = q.z; v[4*i+3] = q.w;                          \
            }                                                            \
        } while (0)

    // window row s feeds output row r (0..3) with weight row (s - r)
    LOADW(0);
    do_pass(acc0, &sw[0 * WSTRIDE], v);

    LOADW(1);
    do_pass(acc0, &sw[1 * WSTRIDE], v);
    do_pass(acc1, &sw[0 * WSTRIDE], v);

    LOADW(2);
    do_pass(acc0, &sw[2 * WSTRIDE], v);
    do_pass(acc1, &sw[1 * WSTRIDE], v);
    do_pass(acc2, &sw[0 * WSTRIDE], v);

    #pragma unroll 1
    for (int s = 3; s <= 20; ++s) {
        LOADW(s);
        const float* __restrict__ w0 = &sw[s * WSTRIDE];
        do_pass(acc0, w0, v);
        do_pass(acc1, w0 - WSTRIDE, v);
        do_pass(acc2, w0 - 2 * WSTRIDE, v);
        do_pass(acc3, w0 - 3 * WSTRIDE, v);
    }

    LOADW(21);
    do_pass(acc1, &sw[20 * WSTRIDE], v);
    do_pass(acc2, &sw[19 * WSTRIDE], v);
    do_pass(acc3, &sw[18 * WSTRIDE], v);

    LOADW(22);
    do_pass(acc2, &sw[20 * WSTRIDE], v);
    do_pass(acc3, &sw[19 * WSTRIDE], v);

    LOADW(23);
    do_pass(acc3, &sw[20 * WSTRIDE], v);

    #undef LOADW

    float* __restrict__ o = out + (size_t)bc * (HW * HW)
                                + (size_t)(by + oy) * HW + (bx + ox);
    *(float4*)(o)              = make_float4(acc0[0], acc0[1], acc0[2], acc0[3]);
    *(float4*)(o + 4)          = make_float4(acc0[4], acc0[5], acc0[6], acc0[7]);
    *(float4*)(o + HW)         = make_float4(acc1[0], acc1[1], acc1[2], acc1[3]);
    *(float4*)(o + HW + 4)     = make_float4(acc1[4], acc1[5], acc1[6], acc1[7]);
    *(float4*)(o + 2 * HW)     = make_float4(acc2[0], acc2[1], acc2[2], acc2[3]);
    *(float4*)(o + 2 * HW + 4) = make_float4(acc2[4], acc2[5], acc2[6], acc2[7]);
    *(float4*)(o + 3 * HW)     = make_float4(acc3[0], acc3[1], acc3[2], acc3[3]);
    *(float4*)(o + 3 * HW + 4) = make_float4(acc3[4], acc3[5], acc3[6], acc3[7]);
}

extern "C" void kernel_launch(void* const* d_in, const int* in_sizes, int n_in,
                              void* d_out, int out_size)
{
    const float* img = (const float*)d_in[0];
    const float* wts = (const float*)d_in[1];
    if (n_in >= 2 && in_sizes[0] == 16 * KS * KS) {   // 7056 -> kernel tensor
        img = (const float*)d_in[1];
        wts = (const float*)d_in[0];
    }

    dim3 grid(HW / TILE_X, HW / TILE_Y, 16 * 3);
    blur21_kernel<<<grid, NT>>>(img, wts, (float*)d_out);
}

// round 11
// speedup vs baseline: 1.1117x; 1.1117x over previous
#include <cuda_runtime.h>

// Blur_by_Kernel: per-batch 21x21 cross-correlation, reflect pad 10.
// input (16,3,768,768) fp32, kernel (16,21,21) fp32.
// out[b,c,y,x] = sum_{ky,kx} in[b,c, refl(y+ky-10), refl(x+kx-10)] * w[b,ky,kx]
//
// R11 = R9 (427.6us best: 128-thread CTAs, 128x32 tile, 6 CTAs/SM, scalar-FFMA
// sliding window, plain row-major tile — R10 proved swizzle is a net loss) plus:
//  (1) vectorized EDGE prologue: bx=0/640 blocks load batched LDG.128 from the
//      clamped aligned span + scalar patch of the 10 reflected columns
//      (edge CTAs were wave stragglers with 60 scalar LDGs).
//  (2) streaming output stores (__stcs): output never re-read; keep L2 for
//      input halo reuse.

namespace {
constexpr int HW   = 768;
constexpr int KS   = 21;
constexpr int PAD  = 10;
constexpr int CPT  = 8;                  // cols per thread
constexpr int RPT  = 4;                  // rows per thread
constexpr int TXN  = 16, TYN = 8;
constexpr int TILE_X = CPT * TXN;        // 128
constexpr int TILE_Y = RPT * TYN;        // 32
constexpr int SM_W = TILE_X + 2 * PAD;   // 148 floats (592B rows)
constexpr int SM_H = TILE_Y + 2 * PAD;   // 52 rows
constexpr int WSTRIDE = 24;              // padded weight row (96B)
constexpr int NT   = TXN * TYN;          // 128
}

__device__ __forceinline__ int refl_y(int gy) {
    return (gy < 0) ? -gy : ((gy >= HW) ? (2 * HW - 2 - gy) : gy);
}

// one weight-row pass: acc[j] += sum_kx v[kx+j] * w[kx]
__device__ __forceinline__ void do_pass(float (&acc)[CPT],
                                        const float* __restrict__ wr,
                                        const float (&v)[28])
{
    #pragma unroll
    for (int g = 0; g < 5; ++g) {
        const float4 w = *(const float4*)(wr + 4 * g);   // broadcast LDS.128
        #pragma unroll
        for (int j = 0; j < CPT; ++j) acc[j] = fmaf(v[4*g + 0 + j], w.x, acc[j]);
        #pragma unroll
        for (int j = 0; j < CPT; ++j) acc[j] = fmaf(v[4*g + 1 + j], w.y, acc[j]);
        #pragma unroll
        for (int j = 0; j < CPT; ++j) acc[j] = fmaf(v[4*g + 2 + j], w.z, acc[j]);
        #pragma unroll
        for (int j = 0; j < CPT; ++j) acc[j] = fmaf(v[4*g + 3 + j], w.w, acc[j]);
    }
    const float wl = wr[20];
    #pragma unroll
    for (int j = 0; j < CPT; ++j) acc[j] = fmaf(v[20 + j], wl, acc[j]);
}

__global__ __launch_bounds__(NT, 6)
void blur21_kernel(const float* __restrict__ in,
                   const float* __restrict__ wts,
                   float* __restrict__ out)
{
    __shared__ float tile[SM_H][SM_W];
    __shared__ float sw[KS * WSTRIDE];

    const int bc  = blockIdx.z;           // b*3 + c
    const int b   = bc / 3;
    const int bx  = blockIdx.x * TILE_X;
    const int by  = blockIdx.y * TILE_Y;
    const int tid = threadIdx.x;

    const float* __restrict__ img = in + (size_t)bc * (HW * HW);

    // weights for this batch, rows padded to WSTRIDE (504 floats)
    for (int i = tid; i < KS * WSTRIDE; i += NT) {
        const int r = i / WSTRIDE, c = i - r * WSTRIDE;
        sw[i] = (c < KS) ? wts[b * (KS * KS) + r * KS + c] : 0.f;
    }

    // ---- vectorized prologue, all blocks ----
    // warp w handles rows w, w+4, ..., w+48 (13 rows, fully unrolled -> MLP).
    {
        const int w  = tid >> 5;
        const int ln = tid & 31;
        const bool left  = (bx == 0);
        const bool right = (bx + TILE_X == HW);
        // aligned gmem float4 base and col mapping:
        //   interior/right: base gx = bx-12, unit u -> c0 = 4u-2, u < 35|38
        //   left:           base gx = 0,     unit u -> c0 = 4u+10, u < 35
        const float* __restrict__ rowbase = img + (left ? 0 : (bx - 12));
        const int cbase = left ? 10 : -2;
        const int umax  = (left || right) ? 35 : 38;

        #pragma unroll
        for (int k = 0; k < 13; ++k) {
            const int r  = w + 4 * k;
            const int gy = refl_y(by + r - PAD);
            const float4* __restrict__ gp =
                (const float4*)(rowbase + (size_t)gy * HW);

            {   // unit u = ln (0..31)
                const float4 q = gp[ln];
                const int c0 = 4 * ln + cbase;
                if (c0 >= 0)          tile[r][c0]     = q.x;
                if (c0 + 1 >= 0)      tile[r][c0 + 1] = q.y;
                if (c0 + 2 < SM_W)    tile[r][c0 + 2] = q.z;
                if (c0 + 3 < SM_W)    tile[r][c0 + 3] = q.w;
            }
            if (ln < umax - 32) {     // unit u = 32+ln
                const float4 q = gp[32 + ln];
                const int c0 = 4 * (32 + ln) + cbase;
                if (c0 < SM_W)        tile[r][c0]     = q.x;
                if (c0 + 1 < SM_W)    tile[r][c0 + 1] = q.y;
                if (c0 + 2 < SM_W)    tile[r][c0 + 2] = q.z;
                if (c0 + 3 < SM_W)    tile[r][c0 + 3] = q.w;
            }
        }

        // scalar patch of the 10 x-reflected columns (edge blocks only):
        //   left : cols 0..9     <- gx = 10 - c          (reflect of -10..-1)
        //   right: cols 138..147 <- gx = 766 - (c - 138) (reflect of 768..777)
        if (left || right) {
            for (int i = tid; i < 10 * SM_H; i += NT) {
                const int r = i / 10;
                const int c = i - r * 10;
                const int gy = refl_y(by + r - PAD);
                if (left)
                    tile[r][c] = img[(size_t)gy * HW + (10 - c)];
                else
                    tile[r][138 + c] = img[(size_t)gy * HW + (766 - c)];
            }
        }
    }
    __syncthreads();

    const int tx = tid & 15;              // 0..15
    const int ty = tid >> 4;              // 0..7
    const int ox = tx * CPT;              // 32B-aligned smem col base
    const int oy = ty * RPT;

    float acc0[CPT], acc1[CPT], acc2[CPT], acc3[CPT];
    #pragma unroll
    for (int j = 0; j < CPT; ++j) {
        acc0[j] = 0.f; acc1[j] = 0.f; acc2[j] = 0.f; acc3[j] = 0.f;
    }

    float v[28];
    #define LOADW(s)                                                     \
        do {                                                             \
            const float4* __restrict__ p =                               \
                (const float4*)&tile[oy + (s)][ox];                      \
            _Pragma("unroll")                                            \
            for (int i = 0; i < 7; ++i) {                                \
                const float4 q = p[i];                                   \
                v[4*i+0] = q.x; v[4*i+1] = q.y;                          \
                v[4*i+2] = q.z; v[4*i+3] = q.w;                          \
            }                                                            \
        } while (0)

    // window row s feeds output row r (0..3) with weight row (s - r)
    LOADW(0);
    do_pass(acc0, &sw[0 * WSTRIDE], v);

    LOADW(1);
    do_pass(acc0, &sw[1 * WSTRIDE], v);
    do_pass(acc1, &sw[0 * WSTRIDE], v);

    LOADW(2);
    do_pass(acc0, &sw[2 * WSTRIDE], v);
    do_pass(acc1, &sw[1 * WSTRIDE], v);
    do_pass(acc2, &sw[0 * WSTRIDE], v);

    #pragma unroll 1
    for (int s = 3; s <= 20; ++s) {
        LOADW(s);
        const float* __restrict__ w0 = &sw[s * WSTRIDE];
        do_pass(acc0, w0, v);
        do_pass(acc1, w0 - WSTRIDE, v);
        do_pass(acc2, w0 - 2 * WSTRIDE, v);
        do_pass(acc3, w0 - 3 * WSTRIDE, v);
    }

    LOADW(21);
    do_pass(acc1, &sw[20 * WSTRIDE], v);
    do_pass(acc2, &sw[19 * WSTRIDE], v);
    do_pass(acc3, &sw[18 * WSTRIDE], v);

    LOADW(22);
    do_pass(acc2, &sw[20 * WSTRIDE], v);
    do_pass(acc3, &sw[19 * WSTRIDE], v);

    LOADW(23);
    do_pass(acc3, &sw[20 * WSTRIDE], v);

    #undef LOADW

    // streaming stores: output is write-once, never re-read
    float* __restrict__ o = out + (size_t)bc * (HW * HW)
                                + (size_t)(by + oy) * HW + (bx + ox);
    __stcs((float4*)(o),              make_float4(acc0[0], acc0[1], acc0[2], acc0[3]));
    __stcs((float4*)(o + 4),          make_float4(acc0[4], acc0[5], acc0[6], acc0[7]));
    __stcs((float4*)(o + HW),         make_float4(acc1[0], acc1[1], acc1[2], acc1[3]));
    __stcs((float4*)(o + HW + 4),     make_float4(acc1[4], acc1[5], acc1[6], acc1[7]));
    __stcs((float4*)(o + 2 * HW),     make_float4(acc2[0], acc2[1], acc2[2], acc2[3]));
    __stcs((float4*)(o + 2 * HW + 4), make_float4(acc2[4], acc2[5], acc2[6], acc2[7]));
    __stcs((float4*)(o + 3 * HW),     make_float4(acc3[0], acc3[1], acc3[2], acc3[3]));
    __stcs((float4*)(o + 3 * HW + 4), make_float4(acc3[4], acc3[5], acc3[6], acc3[7]));
}

extern "C" void kernel_launch(void* const* d_in, const int* in_sizes, int n_in,
                              void* d_out, int out_size)
{
    const float* img = (const float*)d_in[0];
    const float* wts = (const float*)d_in[1];
    if (n_in >= 2 && in_sizes[0] == 16 * KS * KS) {   // 7056 -> kernel tensor
        img = (const float*)d_in[1];
        wts = (const float*)d_in[0];
    }

    dim3 grid(HW / TILE_X, HW / TILE_Y, 16 * 3);
    blur21_kernel<<<grid, NT>>>(img, wts, (float*)d_out);
}